// round 15
// baseline (speedup 1.0000x reference)
#include <cuda_runtime.h>
#include <cuda_fp16.h>
#include <cstdint>

// Problem dims
#define B_  4096
#define D_  4624
#define L_  68
#define E_  1024

// Symmetrized recon K: 68*69/2 = 2346 unique quadratic-form terms, padded to 37*64
#define KS_    2346
#define KS_PAD 2368

// fp16 mma.m16n8k16 + ldmatrix path (tcgen05 unavailable: harness targets compute_103)
// CUTLASS-shape: 256 threads (8 warps = 2/SMSP), warp tile 64x64, CTA tile 128x256,
// ~255-reg budget so ptxas can software-pipeline ldmatrix across kk steps.
#define BM 128
#define BN2 256
#define THREADS 256

// BK=64 tiles for the two large GEMMs
#define BK2 64
#define KP2 36                        // u32 per smem row (32 data + 4 pad)
#define ASTG_U32 (128 * KP2)          // A stage: 128 rows
#define BSTG_U32 (256 * KP2)          // B stage: 256 rows
#define ASTG_B   (ASTG_U32 * 4)       // 18432 B
#define BSTG_B   (BSTG_U32 * 4)       // 36864 B

// BK=32 constants (head GEMM only)
#define KPADH 20
#define STAGEH_U32 (128 * KPADH)
#define STAGE_BYTES (STAGEH_U32 * 4)

// ---- static scratch (no cudaMalloc allowed) ----
__device__ __half   g_x16[(size_t)B_ * D_];
__device__ __half   g_h16[(size_t)B_ * 2 * E_];
__device__ __half   g_w1h[(size_t)2 * E_ * D_];
__device__ __half   g_w2h[(size_t)2 * L_ * E_];
__device__ __half   g_w6s[(size_t)D_ * KS_PAD];
__device__ uint16_t g_pairs[KS_PAD];
__device__ float    g_h51[(size_t)B_ * L_];
__device__ float    g_b1 [2 * E_];

// ============================ helpers ============================
__device__ __forceinline__ void mma_f16(float* c, uint32_t a0, uint32_t a1,
                                        uint32_t a2, uint32_t a3,
                                        uint32_t b0, uint32_t b1) {
    asm volatile(
        "mma.sync.aligned.m16n8k16.row.col.f32.f16.f16.f32 "
        "{%0,%1,%2,%3}, {%4,%5,%6,%7}, {%8,%9}, {%0,%1,%2,%3};\n"
        : "+f"(c[0]), "+f"(c[1]), "+f"(c[2]), "+f"(c[3])
        : "r"(a0), "r"(a1), "r"(a2), "r"(a3), "r"(b0), "r"(b1));
}

__device__ __forceinline__ void ldmatrix_x4(uint32_t& d0, uint32_t& d1,
                                            uint32_t& d2, uint32_t& d3, uint32_t addr) {
    asm volatile("ldmatrix.sync.aligned.m8n8.x4.shared.b16 {%0,%1,%2,%3}, [%4];"
                 : "=r"(d0), "=r"(d1), "=r"(d2), "=r"(d3) : "r"(addr));
}

__device__ __forceinline__ void cp_async16(void* sptr, const void* gptr, int src_size) {
    uint32_t s = (uint32_t)__cvta_generic_to_shared(sptr);
    asm volatile("cp.async.cg.shared.global [%0], [%1], 16, %2;\n"
                 :: "r"(s), "l"(gptr), "r"(src_size));
}
__device__ __forceinline__ void cp_commit() { asm volatile("cp.async.commit_group;\n"); }
template <int N>
__device__ __forceinline__ void cp_wait() { asm volatile("cp.async.wait_group %0;\n" :: "n"(N)); }

__device__ __forceinline__ uint32_t pack_h2(float a, float b) {
    __half2 h = __floats2half2_rn(a, b);
    return *reinterpret_cast<uint32_t*>(&h);
}
__device__ __forceinline__ uint2 cvt4(float4 v) {
    return make_uint2(pack_h2(v.x, v.y), pack_h2(v.z, v.w));
}

// ============================ fused pre-pass ============================
__global__ void prep_all(const float4* __restrict__ x,
                         const float4* __restrict__ w11, const float4* __restrict__ w12,
                         const float4* __restrict__ w21, const float4* __restrict__ w22,
                         const float4* __restrict__ b11, const float4* __restrict__ b12,
                         uint2* __restrict__ x16, uint2* __restrict__ w1h,
                         uint2* __restrict__ w2h, float4* __restrict__ b1)
{
    const int NX  = (B_ * D_) / 4;
    const int NW1 = (E_ * D_) / 4;
    const int NW2 = (L_ * E_) / 4;
    const int NB  = (2 * E_) / 4;
    const int T = NX + 2 * NW1 + 2 * NW2 + NB;
    for (int i = blockIdx.x * blockDim.x + threadIdx.x; i < T;
         i += gridDim.x * blockDim.x) {
        int j = i;
        if (j < NX)  { x16[j] = cvt4(x[j]); continue; }
        j -= NX;
        if (j < NW1) { w1h[j] = cvt4(w11[j]); continue; }
        j -= NW1;
        if (j < NW1) { w1h[NW1 + j] = cvt4(w12[j]); continue; }
        j -= NW1;
        if (j < NW2) { w2h[j] = cvt4(w21[j]); continue; }
        j -= NW2;
        if (j < NW2) { w2h[NW2 + j] = cvt4(w22[j]); continue; }
        j -= NW2;
        if (j < NB / 2) b1[j] = b11[j];
        else            b1[j] = b12[j - NB / 2];
    }
}

// pair table: p -> (i,j), i<=j, upper-triangular row-major
__global__ void build_pairs(uint16_t* __restrict__ pairs) {
    int p = blockIdx.x * blockDim.x + threadIdx.x;
    if (p >= KS_PAD) return;
    if (p >= KS_) { pairs[p] = 0; return; }
    int i = 0, base = 0;
    for (int q = 0; q < L_; q++) {
        int rowlen = L_ - q;
        if (p < base + rowlen) { i = q; break; }
        base += rowlen;
    }
    int j = i + (p - base);
    pairs[p] = (uint16_t)((i << 8) | j);
}

// fold fc6_w rows into symmetric-pair weights
__global__ void build_w6s(const float* __restrict__ w6,
                          const uint16_t* __restrict__ pairs,
                          __half* __restrict__ w6s) {
    __shared__ float row[D_];
    const int o = blockIdx.x;
    const float* src = w6 + (size_t)o * D_;
    for (int i = threadIdx.x; i < D_; i += 256) row[i] = src[i];
    __syncthreads();
    for (int p = threadIdx.x; p < KS_PAD; p += 256) {
        float v = 0.f;
        if (p < KS_) {
            uint16_t pr = pairs[p];
            int i = pr >> 8, j = pr & 255;
            v = row[i * L_ + j];
            if (i != j) v += row[j * L_ + i];
        }
        w6s[(size_t)o * KS_PAD + p] = __float2half_rn(v);
    }
}

// ============================ encoder GEMM (256 thr, warp 64x64, 3+3 stages) ============
// h16 = fp16(relu(x16 @ [fc11|fc12]^T + b1)) ; M=4096, N=2048, K=4624
__global__ void __launch_bounds__(THREADS, 1)
gemm_enc(const __half* __restrict__ A, const __half* __restrict__ W,
         const float* __restrict__ bias, __half* __restrict__ C)
{
    extern __shared__ unsigned char smem_raw[];
    uint32_t* sm = reinterpret_cast<uint32_t*>(smem_raw);
    uint32_t* As = sm;                      // 3 A stages (128 rows each)
    uint32_t* Bs = sm + 3 * ASTG_U32;       // 3 B stages (256 rows each)

    const int K = D_, lda = D_, ldc = 2 * E_;
    const int tid  = threadIdx.x;
    const int lane = tid & 31;
    const int warp = tid >> 5;              // 0..7
    const int wm = warp & 1;                // 2 warps along M (64 rows)
    const int wn = warp >> 1;               // 4 warps along N (64 cols)
    const int grp = lane >> 2, tig = lane & 3;
    const int m0 = blockIdx.y * BM;
    const int n0 = blockIdx.x * BN2;
    const int kt = (K + BK2 - 1) / BK2;     // 73

    const uint32_t As_b = (uint32_t)__cvta_generic_to_shared(As);
    const uint32_t Bs_b = (uint32_t)__cvta_generic_to_shared(Bs);
    const int aRow  = wm * 64 + ((lane >> 3) & 1) * 8 + (lane & 7);  // + mt*16
    const int aColB = (lane >> 4) * 16;
    const int bRow  = wn * 64 + (lane >> 4) * 8 + (lane & 7);        // + nt16*16
    const int bColB = ((lane >> 3) & 1) * 16;

    auto prefetch = [&](int t) {
        const int s  = t % 3;
        const int k0 = t * BK2;
        uint32_t* Ab = As + s * ASTG_U32;
        uint32_t* Bb = Bs + s * BSTG_U32;
        // A: 128 rows x 8 chunks = 1024
#pragma unroll
        for (int i = 0; i < 4; i++) {
            int q = tid + i * 256;
            int r = q >> 3, ch = q & 7;
            int k = k0 + ch * 8;
            cp_async16(Ab + r * KP2 + ch * 4, A + (size_t)(m0 + r) * lda + k,
                       (k < K) ? 16 : 0);
        }
        // B: 256 rows x 8 chunks = 2048
#pragma unroll
        for (int i = 0; i < 8; i++) {
            int q = tid + i * 256;
            int r = q >> 3, ch = q & 7;
            int k = k0 + ch * 8;
            cp_async16(Bb + r * KP2 + ch * 4, W + (size_t)(n0 + r) * K + k,
                       (k < K) ? 16 : 0);
        }
        cp_commit();
    };

    float acc[4][8][4] = {};

    auto compute = [&](int buf) {
        const uint32_t abase = As_b + buf * ASTG_B;
        const uint32_t bbase = Bs_b + buf * BSTG_B;
#pragma unroll
        for (int kk = 0; kk < 4; kk++) {
            const int kb = kk * 32;
            uint32_t a[4][4];
#pragma unroll
            for (int mt = 0; mt < 4; mt++)
                ldmatrix_x4(a[mt][0], a[mt][1], a[mt][2], a[mt][3],
                            abase + (uint32_t)(aRow + mt * 16) * (KP2 * 4) + kb + aColB);
#pragma unroll
            for (int nt16 = 0; nt16 < 4; nt16++) {
                uint32_t b0, b1, b2, b3;
                ldmatrix_x4(b0, b1, b2, b3,
                            bbase + (uint32_t)(bRow + nt16 * 16) * (KP2 * 4) + kb + bColB);
#pragma unroll
                for (int mt = 0; mt < 4; mt++) {
                    mma_f16(acc[mt][nt16 * 2 + 0], a[mt][0], a[mt][1], a[mt][2], a[mt][3], b0, b1);
                    mma_f16(acc[mt][nt16 * 2 + 1], a[mt][0], a[mt][1], a[mt][2], a[mt][3], b2, b3);
                }
            }
        }
    };

    // 3-stage pipeline: fills issued AFTER the barrier; writer stage t+2 is
    // disjoint from reader stages t (this iter) and t-1 (retired by barrier).
    prefetch(0);
    prefetch(1);
    for (int t = 0; t < kt; t++) {
        if (t < kt - 1) cp_wait<1>(); else cp_wait<0>();
        __syncthreads();
        if (t + 2 < kt) prefetch(t + 2);
        compute(t % 3);
    }

    // Epilogue: bias + relu -> fp16 (N=2048, no guards needed)
#pragma unroll
    for (int mt = 0; mt < 4; mt++) {
        int row = m0 + wm * 64 + mt * 16 + grp;
#pragma unroll
        for (int nt = 0; nt < 8; nt++) {
            int col = n0 + wn * 64 + nt * 8 + tig * 2;
#pragma unroll
            for (int half = 0; half < 2; half++) {
                int r = row + half * 8;
                float v0 = acc[mt][nt][half * 2 + 0] + bias[col];
                float v1 = acc[mt][nt][half * 2 + 1] + bias[col + 1];
                v0 = v0 > 0.f ? v0 : 0.f;
                v1 = v1 > 0.f ? v1 : 0.f;
                *reinterpret_cast<uint32_t*>(C + (size_t)r * ldc + col) = pack_h2(v0, v1);
            }
        }
    }
}

// ============================ recon GEMM (256 thr, warp 64x64, 2+2 stages, synth A) =====
// recon = sigmoid(sympairs(h51) @ w6s^T + fc6_b) ; M=4096, N=4624, K=2368
// Safe double-buffer: all stage fills issued AFTER the iteration barrier.
__global__ void __launch_bounds__(THREADS, 1)
gemm_rec(const __half* __restrict__ W, const float* __restrict__ bias,
         const float* __restrict__ h51, const uint16_t* __restrict__ gpairs,
         float* __restrict__ C)
{
    extern __shared__ unsigned char smem_raw[];
    uint32_t* sm = reinterpret_cast<uint32_t*>(smem_raw);
    float*    h51s  = reinterpret_cast<float*>(sm);
    uint16_t* pairS = reinterpret_cast<uint16_t*>(sm + 128 * L_);
    uint32_t* As    = sm + 128 * L_ + KS_PAD / 2;   // 2 stages (128 rows)
    uint32_t* Bs    = As + 2 * ASTG_U32;            // 2 stages (256 rows)

    const int K = KS_PAD, N = D_, Nw = D_, ldc = D_;
    const int tid  = threadIdx.x;
    const int lane = tid & 31;
    const int warp = tid >> 5;
    const int wm = warp & 1, wn = warp >> 1;
    const int grp = lane >> 2, tig = lane & 3;
    const int m0 = blockIdx.y * BM;
    const int n0 = blockIdx.x * BN2;
    const int kt = K / BK2;                 // 37

    for (int idx = tid; idx < BM * L_; idx += THREADS)
        h51s[idx] = h51[(size_t)m0 * L_ + idx];
    for (int idx = tid; idx < KS_PAD; idx += THREADS)
        pairS[idx] = gpairs[idx];
    __syncthreads();

    const uint32_t As_b = (uint32_t)__cvta_generic_to_shared(As);
    const uint32_t Bs_b = (uint32_t)__cvta_generic_to_shared(Bs);
    const int aRow  = wm * 64 + ((lane >> 3) & 1) * 8 + (lane & 7);
    const int aColB = (lane >> 4) * 16;
    const int bRow  = wn * 64 + (lane >> 4) * 8 + (lane & 7);
    const int bColB = ((lane >> 3) & 1) * 16;

    auto synthA = [&](int t) {
        uint32_t* Ab = As + (t & 1) * ASTG_U32;
        const int k0 = t * BK2;
#pragma unroll
        for (int i = 0; i < 4; i++) {
            int q = tid + i * 256;
            int r = q >> 3, ch = q & 7;
            int kb = k0 + ch * 8;
            const float* hr = h51s + r * L_;
            uint32_t v[4];
#pragma unroll
            for (int p = 0; p < 4; p++) {
                uint16_t p0 = pairS[kb + 2 * p];
                uint16_t p1 = pairS[kb + 2 * p + 1];
                float f0 = hr[p0 >> 8] * hr[p0 & 255];
                float f1 = hr[p1 >> 8] * hr[p1 & 255];
                v[p] = pack_h2(f0, f1);
            }
            uint32_t daddr = (uint32_t)__cvta_generic_to_shared(Ab + r * KP2 + ch * 4);
            asm volatile("st.shared.v4.b32 [%0], {%1,%2,%3,%4};"
                         :: "r"(daddr), "r"(v[0]), "r"(v[1]), "r"(v[2]), "r"(v[3])
                         : "memory");
        }
    };

    auto cpB = [&](int t) {
        uint32_t* Bb = Bs + (t & 1) * BSTG_U32;
        const int k0 = t * BK2;
#pragma unroll
        for (int i = 0; i < 8; i++) {
            int q = tid + i * 256;
            int r = q >> 3, ch = q & 7;
            int k = k0 + ch * 8;
            int row = n0 + r;
            const __half* src = W + (size_t)(row < Nw ? row : 0) * K + k;
            cp_async16(Bb + r * KP2 + ch * 4, src, (row < Nw) ? 16 : 0);
        }
        cp_commit();
    };

    float acc[4][8][4] = {};

    auto compute = [&](int buf) {
        const uint32_t abase = As_b + buf * ASTG_B;
        const uint32_t bbase = Bs_b + buf * BSTG_B;
#pragma unroll
        for (int kk = 0; kk < 4; kk++) {
            const int kb = kk * 32;
            uint32_t a[4][4];
#pragma unroll
            for (int mt = 0; mt < 4; mt++)
                ldmatrix_x4(a[mt][0], a[mt][1], a[mt][2], a[mt][3],
                            abase + (uint32_t)(aRow + mt * 16) * (KP2 * 4) + kb + aColB);
#pragma unroll
            for (int nt16 = 0; nt16 < 4; nt16++) {
                uint32_t b0, b1, b2, b3;
                ldmatrix_x4(b0, b1, b2, b3,
                            bbase + (uint32_t)(bRow + nt16 * 16) * (KP2 * 4) + kb + bColB);
#pragma unroll
                for (int mt = 0; mt < 4; mt++) {
                    mma_f16(acc[mt][nt16 * 2 + 0], a[mt][0], a[mt][1], a[mt][2], a[mt][3], b0, b1);
                    mma_f16(acc[mt][nt16 * 2 + 1], a[mt][0], a[mt][1], a[mt][2], a[mt][3], b2, b3);
                }
            }
        }
    };

    synthA(0);           // A(0): visible to all after the t=0 barrier
    cpB(0);              // B(0): completed by the t=0 cp_wait
    for (int t = 0; t < kt; t++) {
        cp_wait<0>();    // B(t) landed (this thread's async group)
        __syncthreads(); // all threads' B(t)/A(t) visible; compute(t-1) retired
        if (t + 1 < kt) {
            cpB(t + 1);      // overwrites B buf of retired compute(t-1) — safe
            synthA(t + 1);   // overwrites A buf of retired compute(t-1) — safe
        }
        compute(t & 1);
    }

    // Epilogue: bias + sigmoid, guarded (N = 4624, last tile partial)
#pragma unroll
    for (int mt = 0; mt < 4; mt++) {
        int row = m0 + wm * 64 + mt * 16 + grp;
#pragma unroll
        for (int nt = 0; nt < 8; nt++) {
            int ncl = wn * 64 + nt * 8 + tig * 2;
#pragma unroll
            for (int half = 0; half < 2; half++) {
                int r   = row + half * 8;
                int col = n0 + ncl;
                if (col < N) {
                    float v0 = acc[mt][nt][half * 2 + 0] + bias[col];
                    C[(size_t)r * ldc + col] = 1.0f / (1.0f + __expf(-v0));
                }
                if (col + 1 < N) {
                    float v1 = acc[mt][nt][half * 2 + 1] + bias[col + 1];
                    C[(size_t)r * ldc + col + 1] = 1.0f / (1.0f + __expf(-v1));
                }
            }
        }
    }
}

// ============================ head GEMM (mu / logvar), fp16, BK=32, 256 thr ============
__global__ void __launch_bounds__(THREADS, 2)
gemm_head(const __half* __restrict__ Abase, const __half* __restrict__ Wbase,
          const float* __restrict__ bias0, const float* __restrict__ bias1,
          float* __restrict__ Cbase, int batchStrideC)
{
    extern __shared__ unsigned char smem_raw[];
    uint32_t* As = reinterpret_cast<uint32_t*>(smem_raw);
    uint32_t* Bs = As + 2 * STAGEH_U32;

    const int tid = threadIdx.x;
    const int m0  = blockIdx.y * BM;
    const int N = L_, K = E_;

    const int z = blockIdx.z;
    const __half* A    = Abase + (size_t)z * E_;
    const __half* W    = Wbase + (size_t)z * L_ * E_;
    const float* bias  = z ? bias1 : bias0;
    float* C           = Cbase + (size_t)z * batchStrideC;

    const int lane = tid & 31;
    const int warp = tid >> 5;
    const int wm = warp & 3, wn = warp >> 2;
    const int grp = lane >> 2, tig = lane & 3;

    const uint32_t As_b = (uint32_t)__cvta_generic_to_shared(As);
    const uint32_t Bs_b = (uint32_t)__cvta_generic_to_shared(Bs);
    const int aRow  = wm * 32 + ((lane >> 3) & 1) * 8 + (lane & 7);
    const int aColB = (lane >> 4) * 16;
    const int bRow  = wn * 64 + (lane >> 4) * 8 + (lane & 7);
    const int bColB = ((lane >> 3) & 1) * 16;

    auto prefetch = [&](int t) {
        const int buf = t & 1;
        const int k0  = t * 32;
        uint32_t* Ab = As + buf * STAGEH_U32;
        uint32_t* Bb = Bs + buf * STAGEH_U32;
#pragma unroll
        for (int i = 0; i < 2; i++) {
            int q = tid + i * 256;
            int r = q >> 2, ch = q & 3;
            int k = k0 + ch * 8;
            cp_async16(Ab + r * KPADH + ch * 4,
                       A + (size_t)(m0 + r) * (2 * E_) + k, 16);
            const __half* src = W + (size_t)(r < N ? r : 0) * K + k;
            cp_async16(Bb + r * KPADH + ch * 4, src, (r < N) ? 16 : 0);
        }
        cp_commit();
    };

    float acc[2][8][4] = {};

    auto compute = [&](int buf) {
        const uint32_t abase = As_b + buf * STAGE_BYTES;
        const uint32_t bbase = Bs_b + buf * STAGE_BYTES;
#pragma unroll
        for (int kk = 0; kk < 2; kk++) {
            const int kb = kk * 32;
            uint32_t a[2][4];
#pragma unroll
            for (int mt = 0; mt < 2; mt++)
                ldmatrix_x4(a[mt][0], a[mt][1], a[mt][2], a[mt][3],
                            abase + (uint32_t)(aRow + mt * 16) * (KPADH * 4) + kb + aColB);
#pragma unroll
            for (int nt16 = 0; nt16 < 4; nt16++) {
                uint32_t b0, b1, b2, b3;
                ldmatrix_x4(b0, b1, b2, b3,
                            bbase + (uint32_t)(bRow + nt16 * 16) * (KPADH * 4) + kb + bColB);
#pragma unroll
                for (int mt = 0; mt < 2; mt++) {
                    mma_f16(acc[mt][nt16 * 2 + 0], a[mt][0], a[mt][1], a[mt][2], a[mt][3], b0, b1);
                    mma_f16(acc[mt][nt16 * 2 + 1], a[mt][0], a[mt][1], a[mt][2], a[mt][3], b2, b3);
                }
            }
        }
    };

    const int kt = K / 32;
    prefetch(0);
    for (int t = 0; t < kt; t++) {
        if (t + 1 < kt) { prefetch(t + 1); cp_wait<1>(); }
        else            { cp_wait<0>(); }
        __syncthreads();
        compute(t & 1);
        __syncthreads();
    }

#pragma unroll
    for (int mt = 0; mt < 2; mt++) {
        int row = m0 + wm * 32 + mt * 16 + grp;
#pragma unroll
        for (int nt = 0; nt < 8; nt++) {
            int ncl = wn * 64 + nt * 8 + tig * 2;
#pragma unroll
            for (int e = 0; e < 4; e++) {
                int r   = row + ((e >= 2) ? 8 : 0);
                int col = ncl + (e & 1);
                if (col < N)
                    C[(size_t)r * N + col] = acc[mt][nt][e] + bias[col];
            }
        }
    }
}

// ============================ mid kernel ============================
__global__ void __launch_bounds__(256, 1)
mid_kernel(const float* __restrict__ mu, const float* __restrict__ logvar,
           const float* __restrict__ eps,
           const float* __restrict__ W3, const float* __restrict__ b3,
           const float* __restrict__ W4, const float* __restrict__ b4,
           const float* __restrict__ W5, const float* __restrict__ b5,
           const float* __restrict__ fcy_w, const float* __restrict__ fcy_b,
           float* __restrict__ h51, float* __restrict__ y)
{
    extern __shared__ unsigned char smem_raw[];
    float* s   = reinterpret_cast<float*>(smem_raw);
    float* sW3 = s;
    float* sW4 = sW3 + L_ * 69;
    float* sW5 = sW4 + L_ * 69;
    float* sb3 = sW5 + L_ * 69;
    float* sb4 = sb3 + L_;
    float* sb5 = sb4 + L_;
    float* zs  = sb5 + L_;
    float* h3s = zs + 8 * L_;
    float* h4s = h3s + 8 * L_;

    const int tid = threadIdx.x;
    for (int idx = tid; idx < L_ * L_; idx += 256) {
        int o = idx / L_, d = idx - o * L_;
        sW3[o * 69 + d] = W3[idx];
        sW4[o * 69 + d] = W4[idx];
        sW5[o * 69 + d] = W5[idx];
    }
    for (int idx = tid; idx < L_; idx += 256) {
        sb3[idx] = b3[idx]; sb4[idx] = b4[idx]; sb5[idx] = b5[idx];
    }
    __syncthreads();

    const int lane = tid & 31, w = tid >> 5;
    const int row = blockIdx.x * 8 + w;
    const float* murow  = mu + (size_t)row * L_;
    const float* lvrow  = logvar + (size_t)row * L_;
    const float* epsrow = eps + (size_t)row * L_;
    float* zw  = zs + w * L_;
    float* h3w = h3s + w * L_;
    float* h4w = h4s + w * L_;

    float yp = 0.f;
    for (int o = lane; o < L_; o += 32) {
        float m_ = murow[o];
        zw[o] = m_ + epsrow[o] * expf(0.5f * lvrow[o]);
        yp += m_ * fcy_w[o];
    }
#pragma unroll
    for (int off = 16; off; off >>= 1) yp += __shfl_xor_sync(0xffffffffu, yp, off);
    if (lane == 0) y[row] = yp + fcy_b[0];
    __syncwarp();

    for (int o = lane; o < L_; o += 32) {
        float sacc = sb3[o];
        const float* wr = sW3 + o * 69;
#pragma unroll 4
        for (int d = 0; d < L_; d++) sacc += zw[d] * wr[d];
        h3w[o] = sacc;                  // branch 0: NO sigmoid
    }
    __syncwarp();
    for (int o = lane; o < L_; o += 32) {
        float sacc = sb4[o];
        const float* wr = sW4 + o * 69;
#pragma unroll 4
        for (int d = 0; d < L_; d++) sacc += h3w[d] * wr[d];
        h4w[o] = 1.0f / (1.0f + expf(-sacc));
    }
    __syncwarp();
    for (int o = lane; o < L_; o += 32) {
        float sacc = sb5[o];
        const float* wr = sW5 + o * 69;
#pragma unroll 4
        for (int d = 0; d < L_; d++) sacc += h4w[d] * wr[d];
        h51[(size_t)row * L_ + o] = sacc;
    }
}

// ============================ launch ============================
extern "C" void kernel_launch(void* const* d_in, const int* in_sizes, int n_in,
                              void* d_out, int out_size)
{
    const float* x      = (const float*)d_in[0];
    const float* eps    = (const float*)d_in[1];
    const float* fc11_w = (const float*)d_in[2];
    const float* fc11_b = (const float*)d_in[3];
    const float* fc12_w = (const float*)d_in[4];
    const float* fc12_b = (const float*)d_in[5];
    const float* fc21_w = (const float*)d_in[6];
    const float* fc21_b = (const float*)d_in[7];
    const float* fc22_w = (const float*)d_in[8];
    const float* fc22_b = (const float*)d_in[9];
    const float* W3     = (const float*)d_in[10];
    const float* b3     = (const float*)d_in[11];
    const float* W4     = (const float*)d_in[12];
    const float* b4     = (const float*)d_in[13];
    const float* W5     = (const float*)d_in[14];
    const float* b5     = (const float*)d_in[15];
    const float* fc6_w  = (const float*)d_in[16];
    const float* fc6_b  = (const float*)d_in[17];
    const float* fcy_w  = (const float*)d_in[18];
    const float* fcy_b  = (const float*)d_in[19];

    float* out   = (float*)d_out;
    float* recon = out;
    float* mu    = out + (size_t)B_ * D_;
    float* lv    = mu + (size_t)B_ * L_;
    float* y     = lv + (size_t)B_ * L_;

    __half*   x16;  cudaGetSymbolAddress((void**)&x16, g_x16);
    __half*   h16;  cudaGetSymbolAddress((void**)&h16, g_h16);
    __half*   w1h;  cudaGetSymbolAddress((void**)&w1h, g_w1h);
    __half*   w2h;  cudaGetSymbolAddress((void**)&w2h, g_w2h);
    __half*   w6s;  cudaGetSymbolAddress((void**)&w6s, g_w6s);
    uint16_t* prs;  cudaGetSymbolAddress((void**)&prs, g_pairs);
    float*    h51;  cudaGetSymbolAddress((void**)&h51, g_h51);
    float*    b1;   cudaGetSymbolAddress((void**)&b1,  g_b1);

    // fused pre-pass (1 launch) + pair table + symmetric weight fold
    prep_all<<<1024, 256>>>((const float4*)x,
                            (const float4*)fc11_w, (const float4*)fc12_w,
                            (const float4*)fc21_w, (const float4*)fc22_w,
                            (const float4*)fc11_b, (const float4*)fc12_b,
                            (uint2*)x16, (uint2*)w1h, (uint2*)w2h, (float4*)b1);
    build_pairs<<<(KS_PAD + 255) / 256, 256>>>(prs);
    build_w6s<<<D_, 256>>>(fc6_w, prs, w6s);

    const size_t smemEnc  = (size_t)3 * (ASTG_B + BSTG_B);                      // 165888
    const size_t smemRec  = (size_t)(128 * L_ * 4) + KS_PAD * 2
                          + 2 * (ASTG_B + BSTG_B);                              // 150144
    const size_t smemHead = (size_t)4 * STAGE_BYTES;                            // 40960
    const size_t smemMid  = (size_t)(3 * L_ * 69 + 3 * L_ + 3 * 8 * L_) * 4;

    cudaFuncSetAttribute(gemm_enc,   cudaFuncAttributeMaxDynamicSharedMemorySize, (int)smemEnc);
    cudaFuncSetAttribute(gemm_rec,   cudaFuncAttributeMaxDynamicSharedMemorySize, (int)smemRec);
    cudaFuncSetAttribute(gemm_head,  cudaFuncAttributeMaxDynamicSharedMemorySize, (int)smemHead);
    cudaFuncSetAttribute(mid_kernel, cudaFuncAttributeMaxDynamicSharedMemorySize, (int)smemMid);

    // 1) h16 = fp16(relu(x @ [fc11|fc12]^T + b))   [4096 x 2048]
    gemm_enc<<<dim3(2 * E_ / BN2, B_ / BM), THREADS, smemEnc>>>(x16, w1h, b1, h16);

    // 2) mu / logvar heads  [4096 x 68], z-batched
    gemm_head<<<dim3(1, B_ / BM, 2), THREADS, smemHead>>>(
        h16, w2h, fc21_b, fc22_b, mu, B_ * L_);

    // 3) reparam + y + decoder branch 0 -> h51
    mid_kernel<<<B_ / 8, 256, smemMid>>>(
        mu, lv, eps, W3, b3, W4, b4, W5, b5, fcy_w, fcy_b, h51, y);

    // 4) recon = sigmoid(sympairs(h51) @ w6s^T + b)  [4096 x 4624], K=2368
    gemm_rec<<<dim3((D_ + BN2 - 1) / BN2, B_ / BM), THREADS, smemRec>>>(
        w6s, fc6_b, h51, prs, recon);
}

// round 16
// speedup vs baseline: 1.1814x; 1.1814x over previous
#include <cuda_runtime.h>
#include <cuda_fp16.h>
#include <cstdint>

// Problem dims
#define B_  4096
#define D_  4624
#define L_  68
#define E_  1024

// Symmetrized recon K: 68*69/2 = 2346 unique quadratic-form terms, padded to 37*64
#define KS_    2346
#define KS_PAD 2368

// fp16 mma.m16n8k16 + ldmatrix path (tcgen05 unavailable: harness targets compute_103).
// NOTE (R15 finding): mma.sync fp16/f32-acc is rate-limited at ~275 TF/s on sm_103a
// (rt ~16cyc/SMSP); the GEMM cores below run at that roofline. This round removes
// recon's in-loop A synthesis instead (precomputed pair products).
#define BM 128
#define BN2 256              // N tile for the two large GEMMs (512-thread CTAs)
#define THREADS2 512
#define THREADS 256

// BK=64 tiles for the two large GEMMs
#define BK2 64
#define KP2 36                        // u32 per smem row (32 data + 4 pad)
#define ASTG_U32 (128 * KP2)          // A stage: 128 rows
#define BSTG_U32 (256 * KP2)          // B stage: 256 rows
#define ASTG_B   (ASTG_U32 * 4)       // 18432 B
#define BSTG_B   (BSTG_U32 * 4)       // 36864 B

// BK=32 constants (head GEMM only, 256 threads)
#define KPADH 20
#define STAGEH_U32 (128 * KPADH)
#define STAGE_BYTES (STAGEH_U32 * 4)

// ---- static scratch (no cudaMalloc allowed) ----
__device__ __half   g_x16[(size_t)B_ * D_];
__device__ __half   g_h16[(size_t)B_ * 2 * E_];
__device__ __half   g_w1h[(size_t)2 * E_ * D_];
__device__ __half   g_w2h[(size_t)2 * L_ * E_];
__device__ __half   g_w6s[(size_t)D_ * KS_PAD];
__device__ __half   g_a16r[(size_t)B_ * KS_PAD];   // precomputed recon A (pair products)
__device__ uint16_t g_pairs[KS_PAD];
__device__ float    g_h51[(size_t)B_ * L_];
__device__ float    g_b1 [2 * E_];

// ============================ helpers ============================
__device__ __forceinline__ void mma_f16(float* c, uint32_t a0, uint32_t a1,
                                        uint32_t a2, uint32_t a3,
                                        uint32_t b0, uint32_t b1) {
    asm volatile(
        "mma.sync.aligned.m16n8k16.row.col.f32.f16.f16.f32 "
        "{%0,%1,%2,%3}, {%4,%5,%6,%7}, {%8,%9}, {%0,%1,%2,%3};\n"
        : "+f"(c[0]), "+f"(c[1]), "+f"(c[2]), "+f"(c[3])
        : "r"(a0), "r"(a1), "r"(a2), "r"(a3), "r"(b0), "r"(b1));
}

__device__ __forceinline__ void ldmatrix_x4(uint32_t& d0, uint32_t& d1,
                                            uint32_t& d2, uint32_t& d3, uint32_t addr) {
    asm volatile("ldmatrix.sync.aligned.m8n8.x4.shared.b16 {%0,%1,%2,%3}, [%4];"
                 : "=r"(d0), "=r"(d1), "=r"(d2), "=r"(d3) : "r"(addr));
}

__device__ __forceinline__ void cp_async16(void* sptr, const void* gptr, int src_size) {
    uint32_t s = (uint32_t)__cvta_generic_to_shared(sptr);
    asm volatile("cp.async.cg.shared.global [%0], [%1], 16, %2;\n"
                 :: "r"(s), "l"(gptr), "r"(src_size));
}
__device__ __forceinline__ void cp_commit() { asm volatile("cp.async.commit_group;\n"); }
template <int N>
__device__ __forceinline__ void cp_wait() { asm volatile("cp.async.wait_group %0;\n" :: "n"(N)); }

__device__ __forceinline__ uint32_t pack_h2(float a, float b) {
    __half2 h = __floats2half2_rn(a, b);
    return *reinterpret_cast<uint32_t*>(&h);
}
__device__ __forceinline__ uint2 cvt4(float4 v) {
    return make_uint2(pack_h2(v.x, v.y), pack_h2(v.z, v.w));
}

// ============================ fused pre-pass ============================
__global__ void prep_all(const float4* __restrict__ x,
                         const float4* __restrict__ w11, const float4* __restrict__ w12,
                         const float4* __restrict__ w21, const float4* __restrict__ w22,
                         const float4* __restrict__ b11, const float4* __restrict__ b12,
                         uint2* __restrict__ x16, uint2* __restrict__ w1h,
                         uint2* __restrict__ w2h, float4* __restrict__ b1)
{
    const int NX  = (B_ * D_) / 4;
    const int NW1 = (E_ * D_) / 4;
    const int NW2 = (L_ * E_) / 4;
    const int NB  = (2 * E_) / 4;
    const int T = NX + 2 * NW1 + 2 * NW2 + NB;
    for (int i = blockIdx.x * blockDim.x + threadIdx.x; i < T;
         i += gridDim.x * blockDim.x) {
        int j = i;
        if (j < NX)  { x16[j] = cvt4(x[j]); continue; }
        j -= NX;
        if (j < NW1) { w1h[j] = cvt4(w11[j]); continue; }
        j -= NW1;
        if (j < NW1) { w1h[NW1 + j] = cvt4(w12[j]); continue; }
        j -= NW1;
        if (j < NW2) { w2h[j] = cvt4(w21[j]); continue; }
        j -= NW2;
        if (j < NW2) { w2h[NW2 + j] = cvt4(w22[j]); continue; }
        j -= NW2;
        if (j < NB / 2) b1[j] = b11[j];
        else            b1[j] = b12[j - NB / 2];
    }
}

// pair table: p -> (i,j), i<=j, upper-triangular row-major
__global__ void build_pairs(uint16_t* __restrict__ pairs) {
    int p = blockIdx.x * blockDim.x + threadIdx.x;
    if (p >= KS_PAD) return;
    if (p >= KS_) { pairs[p] = 0; return; }
    int i = 0, base = 0;
    for (int q = 0; q < L_; q++) {
        int rowlen = L_ - q;
        if (p < base + rowlen) { i = q; break; }
        base += rowlen;
    }
    int j = i + (p - base);
    pairs[p] = (uint16_t)((i << 8) | j);
}

// fold fc6_w rows into symmetric-pair weights
__global__ void build_w6s(const float* __restrict__ w6,
                          const uint16_t* __restrict__ pairs,
                          __half* __restrict__ w6s) {
    __shared__ float row[D_];
    const int o = blockIdx.x;
    const float* src = w6 + (size_t)o * D_;
    for (int i = threadIdx.x; i < D_; i += 256) row[i] = src[i];
    __syncthreads();
    for (int p = threadIdx.x; p < KS_PAD; p += 256) {
        float v = 0.f;
        if (p < KS_) {
            uint16_t pr = pairs[p];
            int i = pr >> 8, j = pr & 255;
            v = row[i * L_ + j];
            if (i != j) v += row[j * L_ + i];
        }
        w6s[(size_t)o * KS_PAD + p] = __float2half_rn(v);
    }
}

// precompute recon A: a16r[m, p] = fp16(h51[m,i] * h51[m,j]) for pair p=(i,j)
__global__ void build_a16r(const float* __restrict__ h51,
                           const uint16_t* __restrict__ pairs,
                           __half* __restrict__ a16r) {
    __shared__ float hrow[L_];
    const int m = blockIdx.x;
    for (int i = threadIdx.x; i < L_; i += 256)
        hrow[i] = h51[(size_t)m * L_ + i];
    __syncthreads();
    for (int p = threadIdx.x; p < KS_PAD; p += 256) {
        uint16_t pr = pairs[p];                 // L2-resident (4.7 KB)
        float v = hrow[pr >> 8] * hrow[pr & 255];
        a16r[(size_t)m * KS_PAD + p] = __float2half_rn(v);
    }
}

// ============================ big GEMM core (512 thr, 128x256 tile, 3+3 stages) ==========
// ACT=0: C(f16) = fp16(relu(acc + bias)),  N multiple of BN2, no guards (encoder)
// ACT=1: C(f32) = sigmoid(acc + bias), guarded cols (recon)
template <int ACT>
__global__ void __launch_bounds__(THREADS2, 1)
gemm_big(const __half* __restrict__ A, int lda,
         const __half* __restrict__ W, const float* __restrict__ bias,
         void* __restrict__ Cout, int ldc, int N, int K, int Nw)
{
    extern __shared__ unsigned char smem_raw[];
    uint32_t* sm = reinterpret_cast<uint32_t*>(smem_raw);
    uint32_t* As = sm;                      // 3 A stages (128 rows each)
    uint32_t* Bs = sm + 3 * ASTG_U32;       // 3 B stages (256 rows each)

    const int tid  = threadIdx.x;
    const int lane = tid & 31;
    const int warp = tid >> 5;              // 0..15
    const int wm = warp & 3;                // 4 warps along M (32 rows)
    const int wn = warp >> 2;               // 4 warps along N (64 cols)
    const int grp = lane >> 2, tig = lane & 3;
    const int m0 = blockIdx.y * BM;
    const int n0 = blockIdx.x * BN2;
    const int kt = (K + BK2 - 1) / BK2;

    const uint32_t As_b = (uint32_t)__cvta_generic_to_shared(As);
    const uint32_t Bs_b = (uint32_t)__cvta_generic_to_shared(Bs);
    const int aRow  = wm * 32 + ((lane >> 3) & 1) * 8 + (lane & 7);
    const int aColB = (lane >> 4) * 16;
    const int bRow  = wn * 64 + (lane >> 4) * 8 + (lane & 7);
    const int bColB = ((lane >> 3) & 1) * 16;

    auto prefetch = [&](int t) {
        const int s  = t % 3;
        const int k0 = t * BK2;
        uint32_t* Ab = As + s * ASTG_U32;
        uint32_t* Bb = Bs + s * BSTG_U32;
        // A: 128 rows x 8 chunks = 1024
#pragma unroll
        for (int i = 0; i < 2; i++) {
            int q = tid + i * 512;
            int r = q >> 3, ch = q & 7;
            int k = k0 + ch * 8;
            cp_async16(Ab + r * KP2 + ch * 4, A + (size_t)(m0 + r) * lda + k,
                       (k < K) ? 16 : 0);
        }
        // B: 256 rows x 8 chunks = 2048
#pragma unroll
        for (int i = 0; i < 4; i++) {
            int q = tid + i * 512;
            int r = q >> 3, ch = q & 7;
            int k = k0 + ch * 8;
            int row = n0 + r;
            const __half* src = W + (size_t)(row < Nw ? row : 0) * K + k;
            cp_async16(Bb + r * KP2 + ch * 4, src,
                       (row < Nw && k < K) ? 16 : 0);
        }
        cp_commit();
    };

    float acc[2][8][4] = {};

    auto compute = [&](int buf) {
        const uint32_t abase = As_b + buf * ASTG_B;
        const uint32_t bbase = Bs_b + buf * BSTG_B;
#pragma unroll
        for (int kk = 0; kk < 4; kk++) {
            const int kb = kk * 32;
            uint32_t a[2][4];
#pragma unroll
            for (int mt = 0; mt < 2; mt++)
                ldmatrix_x4(a[mt][0], a[mt][1], a[mt][2], a[mt][3],
                            abase + (uint32_t)(aRow + mt * 16) * (KP2 * 4) + kb + aColB);
#pragma unroll
            for (int nt16 = 0; nt16 < 4; nt16++) {
                uint32_t b0, b1, b2, b3;
                ldmatrix_x4(b0, b1, b2, b3,
                            bbase + (uint32_t)(bRow + nt16 * 16) * (KP2 * 4) + kb + bColB);
#pragma unroll
                for (int mt = 0; mt < 2; mt++) {
                    mma_f16(acc[mt][nt16 * 2 + 0], a[mt][0], a[mt][1], a[mt][2], a[mt][3], b0, b1);
                    mma_f16(acc[mt][nt16 * 2 + 1], a[mt][0], a[mt][1], a[mt][2], a[mt][3], b2, b3);
                }
            }
        }
    };

    // 3-stage pipeline: fills issued AFTER the barrier; writer stage t+2 is
    // disjoint from reader stages t (this iter) and t-1 (retired by barrier).
    prefetch(0);
    prefetch(1);
    for (int t = 0; t < kt; t++) {
        if (t < kt - 1) cp_wait<1>(); else cp_wait<0>();
        __syncthreads();
        if (t + 2 < kt) prefetch(t + 2);
        compute(t % 3);
    }

    // Epilogue
#pragma unroll
    for (int mt = 0; mt < 2; mt++) {
        int row = m0 + wm * 32 + mt * 16 + grp;
#pragma unroll
        for (int nt = 0; nt < 8; nt++) {
            int ncl = wn * 64 + nt * 8 + tig * 2;
#pragma unroll
            for (int half = 0; half < 2; half++) {
                int r   = row + half * 8;
                int col = n0 + ncl;
                if (ACT == 0) {
                    float v0 = acc[mt][nt][half * 2 + 0] + bias[col];
                    float v1 = acc[mt][nt][half * 2 + 1] + bias[col + 1];
                    v0 = v0 > 0.f ? v0 : 0.f;
                    v1 = v1 > 0.f ? v1 : 0.f;
                    *reinterpret_cast<uint32_t*>(
                        (__half*)Cout + (size_t)r * ldc + col) = pack_h2(v0, v1);
                } else {
                    float* C = (float*)Cout;
                    if (col < N) {
                        float v0 = acc[mt][nt][half * 2 + 0] + bias[col];
                        C[(size_t)r * ldc + col] = 1.0f / (1.0f + __expf(-v0));
                    }
                    if (col + 1 < N) {
                        float v1 = acc[mt][nt][half * 2 + 1] + bias[col + 1];
                        C[(size_t)r * ldc + col + 1] = 1.0f / (1.0f + __expf(-v1));
                    }
                }
            }
        }
    }
}

// ============================ head GEMM (mu / logvar), fp16, BK=32, 256 thr ============
__global__ void __launch_bounds__(THREADS, 2)
gemm_head(const __half* __restrict__ Abase, const __half* __restrict__ Wbase,
          const float* __restrict__ bias0, const float* __restrict__ bias1,
          float* __restrict__ Cbase, int batchStrideC)
{
    extern __shared__ unsigned char smem_raw[];
    uint32_t* As = reinterpret_cast<uint32_t*>(smem_raw);
    uint32_t* Bs = As + 2 * STAGEH_U32;

    const int tid = threadIdx.x;
    const int m0  = blockIdx.y * BM;
    const int N = L_, K = E_;

    const int z = blockIdx.z;
    const __half* A    = Abase + (size_t)z * E_;
    const __half* W    = Wbase + (size_t)z * L_ * E_;
    const float* bias  = z ? bias1 : bias0;
    float* C           = Cbase + (size_t)z * batchStrideC;

    const int lane = tid & 31;
    const int warp = tid >> 5;
    const int wm = warp & 3, wn = warp >> 2;
    const int grp = lane >> 2, tig = lane & 3;

    const uint32_t As_b = (uint32_t)__cvta_generic_to_shared(As);
    const uint32_t Bs_b = (uint32_t)__cvta_generic_to_shared(Bs);
    const int aRow  = wm * 32 + ((lane >> 3) & 1) * 8 + (lane & 7);
    const int aColB = (lane >> 4) * 16;
    const int bRow  = wn * 64 + (lane >> 4) * 8 + (lane & 7);
    const int bColB = ((lane >> 3) & 1) * 16;

    auto prefetch = [&](int t) {
        const int buf = t & 1;
        const int k0  = t * 32;
        uint32_t* Ab = As + buf * STAGEH_U32;
        uint32_t* Bb = Bs + buf * STAGEH_U32;
#pragma unroll
        for (int i = 0; i < 2; i++) {
            int q = tid + i * 256;
            int r = q >> 2, ch = q & 3;
            int k = k0 + ch * 8;
            cp_async16(Ab + r * KPADH + ch * 4,
                       A + (size_t)(m0 + r) * (2 * E_) + k, 16);
            const __half* src = W + (size_t)(r < N ? r : 0) * K + k;
            cp_async16(Bb + r * KPADH + ch * 4, src, (r < N) ? 16 : 0);
        }
        cp_commit();
    };

    float acc[2][8][4] = {};

    auto compute = [&](int buf) {
        const uint32_t abase = As_b + buf * STAGE_BYTES;
        const uint32_t bbase = Bs_b + buf * STAGE_BYTES;
#pragma unroll
        for (int kk = 0; kk < 2; kk++) {
            const int kb = kk * 32;
            uint32_t a[2][4];
#pragma unroll
            for (int mt = 0; mt < 2; mt++)
                ldmatrix_x4(a[mt][0], a[mt][1], a[mt][2], a[mt][3],
                            abase + (uint32_t)(aRow + mt * 16) * (KPADH * 4) + kb + aColB);
#pragma unroll
            for (int nt16 = 0; nt16 < 4; nt16++) {
                uint32_t b0, b1, b2, b3;
                ldmatrix_x4(b0, b1, b2, b3,
                            bbase + (uint32_t)(bRow + nt16 * 16) * (KPADH * 4) + kb + bColB);
#pragma unroll
                for (int mt = 0; mt < 2; mt++) {
                    mma_f16(acc[mt][nt16 * 2 + 0], a[mt][0], a[mt][1], a[mt][2], a[mt][3], b0, b1);
                    mma_f16(acc[mt][nt16 * 2 + 1], a[mt][0], a[mt][1], a[mt][2], a[mt][3], b2, b3);
                }
            }
        }
    };

    const int kt = K / 32;
    prefetch(0);
    for (int t = 0; t < kt; t++) {
        if (t + 1 < kt) { prefetch(t + 1); cp_wait<1>(); }
        else            { cp_wait<0>(); }
        __syncthreads();
        compute(t & 1);
        __syncthreads();
    }

#pragma unroll
    for (int mt = 0; mt < 2; mt++) {
        int row = m0 + wm * 32 + mt * 16 + grp;
#pragma unroll
        for (int nt = 0; nt < 8; nt++) {
            int ncl = wn * 64 + nt * 8 + tig * 2;
#pragma unroll
            for (int e = 0; e < 4; e++) {
                int r   = row + ((e >= 2) ? 8 : 0);
                int col = ncl + (e & 1);
                if (col < N)
                    C[(size_t)r * N + col] = acc[mt][nt][e] + bias[col];
            }
        }
    }
}

// ============================ mid kernel ============================
__global__ void __launch_bounds__(256, 1)
mid_kernel(const float* __restrict__ mu, const float* __restrict__ logvar,
           const float* __restrict__ eps,
           const float* __restrict__ W3, const float* __restrict__ b3,
           const float* __restrict__ W4, const float* __restrict__ b4,
           const float* __restrict__ W5, const float* __restrict__ b5,
           const float* __restrict__ fcy_w, const float* __restrict__ fcy_b,
           float* __restrict__ h51, float* __restrict__ y)
{
    extern __shared__ unsigned char smem_raw[];
    float* s   = reinterpret_cast<float*>(smem_raw);
    float* sW3 = s;
    float* sW4 = sW3 + L_ * 69;
    float* sW5 = sW4 + L_ * 69;
    float* sb3 = sW5 + L_ * 69;
    float* sb4 = sb3 + L_;
    float* sb5 = sb4 + L_;
    float* zs  = sb5 + L_;
    float* h3s = zs + 8 * L_;
    float* h4s = h3s + 8 * L_;

    const int tid = threadIdx.x;
    for (int idx = tid; idx < L_ * L_; idx += 256) {
        int o = idx / L_, d = idx - o * L_;
        sW3[o * 69 + d] = W3[idx];
        sW4[o * 69 + d] = W4[idx];
        sW5[o * 69 + d] = W5[idx];
    }
    for (int idx = tid; idx < L_; idx += 256) {
        sb3[idx] = b3[idx]; sb4[idx] = b4[idx]; sb5[idx] = b5[idx];
    }
    __syncthreads();

    const int lane = tid & 31, w = tid >> 5;
    const int row = blockIdx.x * 8 + w;
    const float* murow  = mu + (size_t)row * L_;
    const float* lvrow  = logvar + (size_t)row * L_;
    const float* epsrow = eps + (size_t)row * L_;
    float* zw  = zs + w * L_;
    float* h3w = h3s + w * L_;
    float* h4w = h4s + w * L_;

    float yp = 0.f;
    for (int o = lane; o < L_; o += 32) {
        float m_ = murow[o];
        zw[o] = m_ + epsrow[o] * expf(0.5f * lvrow[o]);
        yp += m_ * fcy_w[o];
    }
#pragma unroll
    for (int off = 16; off; off >>= 1) yp += __shfl_xor_sync(0xffffffffu, yp, off);
    if (lane == 0) y[row] = yp + fcy_b[0];
    __syncwarp();

    for (int o = lane; o < L_; o += 32) {
        float sacc = sb3[o];
        const float* wr = sW3 + o * 69;
#pragma unroll 4
        for (int d = 0; d < L_; d++) sacc += zw[d] * wr[d];
        h3w[o] = sacc;                  // branch 0: NO sigmoid
    }
    __syncwarp();
    for (int o = lane; o < L_; o += 32) {
        float sacc = sb4[o];
        const float* wr = sW4 + o * 69;
#pragma unroll 4
        for (int d = 0; d < L_; d++) sacc += h3w[d] * wr[d];
        h4w[o] = 1.0f / (1.0f + expf(-sacc));
    }
    __syncwarp();
    for (int o = lane; o < L_; o += 32) {
        float sacc = sb5[o];
        const float* wr = sW5 + o * 69;
#pragma unroll 4
        for (int d = 0; d < L_; d++) sacc += h4w[d] * wr[d];
        h51[(size_t)row * L_ + o] = sacc;
    }
}

// ============================ launch ============================
extern "C" void kernel_launch(void* const* d_in, const int* in_sizes, int n_in,
                              void* d_out, int out_size)
{
    const float* x      = (const float*)d_in[0];
    const float* eps    = (const float*)d_in[1];
    const float* fc11_w = (const float*)d_in[2];
    const float* fc11_b = (const float*)d_in[3];
    const float* fc12_w = (const float*)d_in[4];
    const float* fc12_b = (const float*)d_in[5];
    const float* fc21_w = (const float*)d_in[6];
    const float* fc21_b = (const float*)d_in[7];
    const float* fc22_w = (const float*)d_in[8];
    const float* fc22_b = (const float*)d_in[9];
    const float* W3     = (const float*)d_in[10];
    const float* b3     = (const float*)d_in[11];
    const float* W4     = (const float*)d_in[12];
    const float* b4     = (const float*)d_in[13];
    const float* W5     = (const float*)d_in[14];
    const float* b5     = (const float*)d_in[15];
    const float* fc6_w  = (const float*)d_in[16];
    const float* fc6_b  = (const float*)d_in[17];
    const float* fcy_w  = (const float*)d_in[18];
    const float* fcy_b  = (const float*)d_in[19];

    float* out   = (float*)d_out;
    float* recon = out;
    float* mu    = out + (size_t)B_ * D_;
    float* lv    = mu + (size_t)B_ * L_;
    float* y     = lv + (size_t)B_ * L_;

    __half*   x16;  cudaGetSymbolAddress((void**)&x16, g_x16);
    __half*   h16;  cudaGetSymbolAddress((void**)&h16, g_h16);
    __half*   w1h;  cudaGetSymbolAddress((void**)&w1h, g_w1h);
    __half*   w2h;  cudaGetSymbolAddress((void**)&w2h, g_w2h);
    __half*   w6s;  cudaGetSymbolAddress((void**)&w6s, g_w6s);
    __half*   a16r; cudaGetSymbolAddress((void**)&a16r, g_a16r);
    uint16_t* prs;  cudaGetSymbolAddress((void**)&prs, g_pairs);
    float*    h51;  cudaGetSymbolAddress((void**)&h51, g_h51);
    float*    b1;   cudaGetSymbolAddress((void**)&b1,  g_b1);

    // fused pre-pass (1 launch) + pair table + symmetric weight fold
    prep_all<<<1024, 256>>>((const float4*)x,
                            (const float4*)fc11_w, (const float4*)fc12_w,
                            (const float4*)fc21_w, (const float4*)fc22_w,
                            (const float4*)fc11_b, (const float4*)fc12_b,
                            (uint2*)x16, (uint2*)w1h, (uint2*)w2h, (float4*)b1);
    build_pairs<<<(KS_PAD + 255) / 256, 256>>>(prs);
    build_w6s<<<D_, 256>>>(fc6_w, prs, w6s);

    const size_t smemBig  = (size_t)3 * (ASTG_B + BSTG_B);                      // 165888
    const size_t smemHead = (size_t)4 * STAGE_BYTES;                            // 40960
    const size_t smemMid  = (size_t)(3 * L_ * 69 + 3 * L_ + 3 * 8 * L_) * 4;

    cudaFuncSetAttribute(gemm_big<0>, cudaFuncAttributeMaxDynamicSharedMemorySize, (int)smemBig);
    cudaFuncSetAttribute(gemm_big<1>, cudaFuncAttributeMaxDynamicSharedMemorySize, (int)smemBig);
    cudaFuncSetAttribute(gemm_head,   cudaFuncAttributeMaxDynamicSharedMemorySize, (int)smemHead);
    cudaFuncSetAttribute(mid_kernel,  cudaFuncAttributeMaxDynamicSharedMemorySize, (int)smemMid);

    // 1) h16 = fp16(relu(x @ [fc11|fc12]^T + b))   [4096 x 2048]
    gemm_big<0><<<dim3(2 * E_ / BN2, B_ / BM), THREADS2, smemBig>>>(
        x16, D_, w1h, b1, h16, 2 * E_, 2 * E_, D_, 2 * E_);

    // 2) mu / logvar heads  [4096 x 68], z-batched
    gemm_head<<<dim3(1, B_ / BM, 2), THREADS, smemHead>>>(
        h16, w2h, fc21_b, fc22_b, mu, B_ * L_);

    // 3) reparam + y + decoder branch 0 -> h51
    mid_kernel<<<B_ / 8, 256, smemMid>>>(
        mu, lv, eps, W3, b3, W4, b4, W5, b5, fcy_w, fcy_b, h51, y);

    // 3b) materialize recon A: pair products of h51 (fp16)
    build_a16r<<<B_, 256>>>(h51, prs, a16r);

    // 4) recon = sigmoid(a16r @ w6s^T + b)  [4096 x 4624], K=2368
    gemm_big<1><<<dim3((D_ + BN2 - 1) / BN2, B_ / BM), THREADS2, smemBig>>>(
        a16r, KS_PAD, w6s, fc6_b, recon, D_, D_, KS_PAD, D_);
}

// round 17
// speedup vs baseline: 1.1857x; 1.0037x over previous
#include <cuda_runtime.h>
#include <cuda_fp16.h>
#include <cstdint>

// Problem dims
#define B_  4096
#define D_  4624
#define L_  68
#define E_  1024

// Symmetrized recon K: 68*69/2 = 2346 unique quadratic-form terms, padded to 37*64
#define KS_    2346
#define KS_PAD 2368

// fp16 mma.m16n8k16 + ldmatrix path (tcgen05 unavailable: harness targets compute_103).
// R15/R16 finding: mma.sync fp16/f32-acc is rate-limited ~275 TF/s on sm_103a
// (rt ~16 cyc/SMSP); both big GEMMs run at that roofline. f16-acc (2x) rejected:
// quantified rounding (+2e-3) exceeds the 1e-3 budget. This round trims the
// non-GEMM tail: 3-stage head pipeline + fused mid/a16r.
#define BM 128
#define BN2 256
#define THREADS2 512
#define THREADS 256

// BK=64 tiles for the two large GEMMs
#define BK2 64
#define KP2 36                        // u32 per smem row (32 data + 4 pad)
#define ASTG_U32 (128 * KP2)
#define BSTG_U32 (256 * KP2)
#define ASTG_B   (ASTG_U32 * 4)       // 18432 B
#define BSTG_B   (BSTG_U32 * 4)       // 36864 B

// BK=32 constants (head GEMM, 256 threads, 3 stages)
#define KPADH 20
#define STAGEH_U32 (128 * KPADH)
#define STAGE_BYTES (STAGEH_U32 * 4)

// ---- static scratch (no cudaMalloc allowed) ----
__device__ __half   g_x16[(size_t)B_ * D_];
__device__ __half   g_h16[(size_t)B_ * 2 * E_];
__device__ __half   g_w1h[(size_t)2 * E_ * D_];
__device__ __half   g_w2h[(size_t)2 * L_ * E_];
__device__ __half   g_w6s[(size_t)D_ * KS_PAD];
__device__ __half   g_a16r[(size_t)B_ * KS_PAD];   // precomputed recon A (pair products)
__device__ uint16_t g_pairs[KS_PAD];
__device__ float    g_b1 [2 * E_];

// ============================ helpers ============================
__device__ __forceinline__ void mma_f16(float* c, uint32_t a0, uint32_t a1,
                                        uint32_t a2, uint32_t a3,
                                        uint32_t b0, uint32_t b1) {
    asm volatile(
        "mma.sync.aligned.m16n8k16.row.col.f32.f16.f16.f32 "
        "{%0,%1,%2,%3}, {%4,%5,%6,%7}, {%8,%9}, {%0,%1,%2,%3};\n"
        : "+f"(c[0]), "+f"(c[1]), "+f"(c[2]), "+f"(c[3])
        : "r"(a0), "r"(a1), "r"(a2), "r"(a3), "r"(b0), "r"(b1));
}

__device__ __forceinline__ void ldmatrix_x4(uint32_t& d0, uint32_t& d1,
                                            uint32_t& d2, uint32_t& d3, uint32_t addr) {
    asm volatile("ldmatrix.sync.aligned.m8n8.x4.shared.b16 {%0,%1,%2,%3}, [%4];"
                 : "=r"(d0), "=r"(d1), "=r"(d2), "=r"(d3) : "r"(addr));
}

__device__ __forceinline__ void cp_async16(void* sptr, const void* gptr, int src_size) {
    uint32_t s = (uint32_t)__cvta_generic_to_shared(sptr);
    asm volatile("cp.async.cg.shared.global [%0], [%1], 16, %2;\n"
                 :: "r"(s), "l"(gptr), "r"(src_size));
}
__device__ __forceinline__ void cp_commit() { asm volatile("cp.async.commit_group;\n"); }
template <int N>
__device__ __forceinline__ void cp_wait() { asm volatile("cp.async.wait_group %0;\n" :: "n"(N)); }

__device__ __forceinline__ uint32_t pack_h2(float a, float b) {
    __half2 h = __floats2half2_rn(a, b);
    return *reinterpret_cast<uint32_t*>(&h);
}
__device__ __forceinline__ uint2 cvt4(float4 v) {
    return make_uint2(pack_h2(v.x, v.y), pack_h2(v.z, v.w));
}

// ============================ fused pre-pass ============================
__global__ void prep_all(const float4* __restrict__ x,
                         const float4* __restrict__ w11, const float4* __restrict__ w12,
                         const float4* __restrict__ w21, const float4* __restrict__ w22,
                         const float4* __restrict__ b11, const float4* __restrict__ b12,
                         uint2* __restrict__ x16, uint2* __restrict__ w1h,
                         uint2* __restrict__ w2h, float4* __restrict__ b1)
{
    const int NX  = (B_ * D_) / 4;
    const int NW1 = (E_ * D_) / 4;
    const int NW2 = (L_ * E_) / 4;
    const int NB  = (2 * E_) / 4;
    const int T = NX + 2 * NW1 + 2 * NW2 + NB;
    for (int i = blockIdx.x * blockDim.x + threadIdx.x; i < T;
         i += gridDim.x * blockDim.x) {
        int j = i;
        if (j < NX)  { x16[j] = cvt4(x[j]); continue; }
        j -= NX;
        if (j < NW1) { w1h[j] = cvt4(w11[j]); continue; }
        j -= NW1;
        if (j < NW1) { w1h[NW1 + j] = cvt4(w12[j]); continue; }
        j -= NW1;
        if (j < NW2) { w2h[j] = cvt4(w21[j]); continue; }
        j -= NW2;
        if (j < NW2) { w2h[NW2 + j] = cvt4(w22[j]); continue; }
        j -= NW2;
        if (j < NB / 2) b1[j] = b11[j];
        else            b1[j] = b12[j - NB / 2];
    }
}

// pair table: p -> (i,j), i<=j, upper-triangular row-major
__global__ void build_pairs(uint16_t* __restrict__ pairs) {
    int p = blockIdx.x * blockDim.x + threadIdx.x;
    if (p >= KS_PAD) return;
    if (p >= KS_) { pairs[p] = 0; return; }
    int i = 0, base = 0;
    for (int q = 0; q < L_; q++) {
        int rowlen = L_ - q;
        if (p < base + rowlen) { i = q; break; }
        base += rowlen;
    }
    int j = i + (p - base);
    pairs[p] = (uint16_t)((i << 8) | j);
}

// fold fc6_w rows into symmetric-pair weights
__global__ void build_w6s(const float* __restrict__ w6,
                          const uint16_t* __restrict__ pairs,
                          __half* __restrict__ w6s) {
    __shared__ float row[D_];
    const int o = blockIdx.x;
    const float* src = w6 + (size_t)o * D_;
    for (int i = threadIdx.x; i < D_; i += 256) row[i] = src[i];
    __syncthreads();
    for (int p = threadIdx.x; p < KS_PAD; p += 256) {
        float v = 0.f;
        if (p < KS_) {
            uint16_t pr = pairs[p];
            int i = pr >> 8, j = pr & 255;
            v = row[i * L_ + j];
            if (i != j) v += row[j * L_ + i];
        }
        w6s[(size_t)o * KS_PAD + p] = __float2half_rn(v);
    }
}

// ============================ big GEMM core (512 thr, 128x256 tile, 3+3 stages) ==========
// ACT=0: C(f16) = fp16(relu(acc + bias))  (encoder)
// ACT=1: C(f32) = sigmoid(acc + bias), guarded cols (recon)
template <int ACT>
__global__ void __launch_bounds__(THREADS2, 1)
gemm_big(const __half* __restrict__ A, int lda,
         const __half* __restrict__ W, const float* __restrict__ bias,
         void* __restrict__ Cout, int ldc, int N, int K, int Nw)
{
    extern __shared__ unsigned char smem_raw[];
    uint32_t* sm = reinterpret_cast<uint32_t*>(smem_raw);
    uint32_t* As = sm;
    uint32_t* Bs = sm + 3 * ASTG_U32;

    const int tid  = threadIdx.x;
    const int lane = tid & 31;
    const int warp = tid >> 5;
    const int wm = warp & 3, wn = warp >> 2;
    const int grp = lane >> 2, tig = lane & 3;
    const int m0 = blockIdx.y * BM;
    const int n0 = blockIdx.x * BN2;
    const int kt = (K + BK2 - 1) / BK2;

    const uint32_t As_b = (uint32_t)__cvta_generic_to_shared(As);
    const uint32_t Bs_b = (uint32_t)__cvta_generic_to_shared(Bs);
    const int aRow  = wm * 32 + ((lane >> 3) & 1) * 8 + (lane & 7);
    const int aColB = (lane >> 4) * 16;
    const int bRow  = wn * 64 + (lane >> 4) * 8 + (lane & 7);
    const int bColB = ((lane >> 3) & 1) * 16;

    auto prefetch = [&](int t) {
        const int s  = t % 3;
        const int k0 = t * BK2;
        uint32_t* Ab = As + s * ASTG_U32;
        uint32_t* Bb = Bs + s * BSTG_U32;
#pragma unroll
        for (int i = 0; i < 2; i++) {
            int q = tid + i * 512;
            int r = q >> 3, ch = q & 7;
            int k = k0 + ch * 8;
            cp_async16(Ab + r * KP2 + ch * 4, A + (size_t)(m0 + r) * lda + k,
                       (k < K) ? 16 : 0);
        }
#pragma unroll
        for (int i = 0; i < 4; i++) {
            int q = tid + i * 512;
            int r = q >> 3, ch = q & 7;
            int k = k0 + ch * 8;
            int row = n0 + r;
            const __half* src = W + (size_t)(row < Nw ? row : 0) * K + k;
            cp_async16(Bb + r * KP2 + ch * 4, src,
                       (row < Nw && k < K) ? 16 : 0);
        }
        cp_commit();
    };

    float acc[2][8][4] = {};

    auto compute = [&](int buf) {
        const uint32_t abase = As_b + buf * ASTG_B;
        const uint32_t bbase = Bs_b + buf * BSTG_B;
#pragma unroll
        for (int kk = 0; kk < 4; kk++) {
            const int kb = kk * 32;
            uint32_t a[2][4];
#pragma unroll
            for (int mt = 0; mt < 2; mt++)
                ldmatrix_x4(a[mt][0], a[mt][1], a[mt][2], a[mt][3],
                            abase + (uint32_t)(aRow + mt * 16) * (KP2 * 4) + kb + aColB);
#pragma unroll
            for (int nt16 = 0; nt16 < 4; nt16++) {
                uint32_t b0, b1, b2, b3;
                ldmatrix_x4(b0, b1, b2, b3,
                            bbase + (uint32_t)(bRow + nt16 * 16) * (KP2 * 4) + kb + bColB);
#pragma unroll
                for (int mt = 0; mt < 2; mt++) {
                    mma_f16(acc[mt][nt16 * 2 + 0], a[mt][0], a[mt][1], a[mt][2], a[mt][3], b0, b1);
                    mma_f16(acc[mt][nt16 * 2 + 1], a[mt][0], a[mt][1], a[mt][2], a[mt][3], b2, b3);
                }
            }
        }
    };

    prefetch(0);
    prefetch(1);
    for (int t = 0; t < kt; t++) {
        if (t < kt - 1) cp_wait<1>(); else cp_wait<0>();
        __syncthreads();
        if (t + 2 < kt) prefetch(t + 2);
        compute(t % 3);
    }

#pragma unroll
    for (int mt = 0; mt < 2; mt++) {
        int row = m0 + wm * 32 + mt * 16 + grp;
#pragma unroll
        for (int nt = 0; nt < 8; nt++) {
            int ncl = wn * 64 + nt * 8 + tig * 2;
#pragma unroll
            for (int half = 0; half < 2; half++) {
                int r   = row + half * 8;
                int col = n0 + ncl;
                if (ACT == 0) {
                    float v0 = acc[mt][nt][half * 2 + 0] + bias[col];
                    float v1 = acc[mt][nt][half * 2 + 1] + bias[col + 1];
                    v0 = v0 > 0.f ? v0 : 0.f;
                    v1 = v1 > 0.f ? v1 : 0.f;
                    *reinterpret_cast<uint32_t*>(
                        (__half*)Cout + (size_t)r * ldc + col) = pack_h2(v0, v1);
                } else {
                    float* C = (float*)Cout;
                    if (col < N) {
                        float v0 = acc[mt][nt][half * 2 + 0] + bias[col];
                        C[(size_t)r * ldc + col] = 1.0f / (1.0f + __expf(-v0));
                    }
                    if (col + 1 < N) {
                        float v1 = acc[mt][nt][half * 2 + 1] + bias[col + 1];
                        C[(size_t)r * ldc + col + 1] = 1.0f / (1.0f + __expf(-v1));
                    }
                }
            }
        }
    }
}

// ============================ head GEMM (mu / logvar), 3-stage single-barrier ============
__global__ void __launch_bounds__(THREADS, 2)
gemm_head(const __half* __restrict__ Abase, const __half* __restrict__ Wbase,
          const float* __restrict__ bias0, const float* __restrict__ bias1,
          float* __restrict__ Cbase, int batchStrideC)
{
    extern __shared__ unsigned char smem_raw[];
    uint32_t* As = reinterpret_cast<uint32_t*>(smem_raw);          // 3 stages
    uint32_t* Bs = As + 3 * STAGEH_U32;                            // 3 stages

    const int tid = threadIdx.x;
    const int m0  = blockIdx.y * BM;
    const int N = L_, K = E_;

    const int z = blockIdx.z;
    const __half* A    = Abase + (size_t)z * E_;
    const __half* W    = Wbase + (size_t)z * L_ * E_;
    const float* bias  = z ? bias1 : bias0;
    float* C           = Cbase + (size_t)z * batchStrideC;

    const int lane = tid & 31;
    const int warp = tid >> 5;
    const int wm = warp & 3, wn = warp >> 2;
    const int grp = lane >> 2, tig = lane & 3;

    const uint32_t As_b = (uint32_t)__cvta_generic_to_shared(As);
    const uint32_t Bs_b = (uint32_t)__cvta_generic_to_shared(Bs);
    const int aRow  = wm * 32 + ((lane >> 3) & 1) * 8 + (lane & 7);
    const int aColB = (lane >> 4) * 16;
    const int bRow  = wn * 64 + (lane >> 4) * 8 + (lane & 7);
    const int bColB = ((lane >> 3) & 1) * 16;

    auto prefetch = [&](int t) {
        const int s  = t % 3;
        const int k0 = t * 32;
        uint32_t* Ab = As + s * STAGEH_U32;
        uint32_t* Bb = Bs + s * STAGEH_U32;
#pragma unroll
        for (int i = 0; i < 2; i++) {
            int q = tid + i * 256;
            int r = q >> 2, ch = q & 3;
            int k = k0 + ch * 8;
            cp_async16(Ab + r * KPADH + ch * 4,
                       A + (size_t)(m0 + r) * (2 * E_) + k, 16);
            const __half* src = W + (size_t)(r < N ? r : 0) * K + k;
            cp_async16(Bb + r * KPADH + ch * 4, src, (r < N) ? 16 : 0);
        }
        cp_commit();
    };

    float acc[2][8][4] = {};

    auto compute = [&](int buf) {
        const uint32_t abase = As_b + buf * STAGE_BYTES;
        const uint32_t bbase = Bs_b + buf * STAGE_BYTES;
#pragma unroll
        for (int kk = 0; kk < 2; kk++) {
            const int kb = kk * 32;
            uint32_t a[2][4];
#pragma unroll
            for (int mt = 0; mt < 2; mt++)
                ldmatrix_x4(a[mt][0], a[mt][1], a[mt][2], a[mt][3],
                            abase + (uint32_t)(aRow + mt * 16) * (KPADH * 4) + kb + aColB);
#pragma unroll
            for (int nt16 = 0; nt16 < 4; nt16++) {
                uint32_t b0, b1, b2, b3;
                ldmatrix_x4(b0, b1, b2, b3,
                            bbase + (uint32_t)(bRow + nt16 * 16) * (KPADH * 4) + kb + bColB);
#pragma unroll
                for (int mt = 0; mt < 2; mt++) {
                    mma_f16(acc[mt][nt16 * 2 + 0], a[mt][0], a[mt][1], a[mt][2], a[mt][3], b0, b1);
                    mma_f16(acc[mt][nt16 * 2 + 1], a[mt][0], a[mt][1], a[mt][2], a[mt][3], b2, b3);
                }
            }
        }
    };

    const int kt = K / 32;                  // 32
    prefetch(0);
    prefetch(1);
    for (int t = 0; t < kt; t++) {
        if (t < kt - 1) cp_wait<1>(); else cp_wait<0>();
        __syncthreads();
        if (t + 2 < kt) prefetch(t + 2);
        compute(t % 3);
    }

#pragma unroll
    for (int mt = 0; mt < 2; mt++) {
        int row = m0 + wm * 32 + mt * 16 + grp;
#pragma unroll
        for (int nt = 0; nt < 8; nt++) {
            int ncl = wn * 64 + nt * 8 + tig * 2;
#pragma unroll
            for (int e = 0; e < 4; e++) {
                int r   = row + ((e >= 2) ? 8 : 0);
                int col = ncl + (e & 1);
                if (col < N)
                    C[(size_t)r * N + col] = acc[mt][nt][e] + bias[col];
            }
        }
    }
}

// ============================ fused mid + a16r kernel ============================
// z = mu + eps*exp(0.5*logvar); y = mu@fcy^T+b;
// h3_0 = z@W3[0]^T+b3[0] (no sigmoid); h4_0 = sigmoid(h3_0@W4[0]^T+b4[0]);
// h51 = h4_0@W5[0]^T+b5[0] (kept in smem); then a16r[m,p] = fp16(h51_i * h51_j).
__global__ void __launch_bounds__(256, 1)
mid_a16r_kernel(const float* __restrict__ mu, const float* __restrict__ logvar,
                const float* __restrict__ eps,
                const float* __restrict__ W3, const float* __restrict__ b3,
                const float* __restrict__ W4, const float* __restrict__ b4,
                const float* __restrict__ W5, const float* __restrict__ b5,
                const float* __restrict__ fcy_w, const float* __restrict__ fcy_b,
                const uint16_t* __restrict__ gpairs,
                __half* __restrict__ a16r, float* __restrict__ y)
{
    extern __shared__ unsigned char smem_raw[];
    float* s   = reinterpret_cast<float*>(smem_raw);
    float* sW3 = s;                    // 68*69 padded
    float* sW4 = sW3 + L_ * 69;
    float* sW5 = sW4 + L_ * 69;
    float* sb3 = sW5 + L_ * 69;
    float* sb4 = sb3 + L_;
    float* sb5 = sb4 + L_;
    float* zs  = sb5 + L_;             // 8*68
    float* h3s = zs + 8 * L_;
    float* h4s = h3s + 8 * L_;
    float* h5s = h4s + 8 * L_;         // 8*68 (h51 rows, block-local)
    uint16_t* prS = reinterpret_cast<uint16_t*>(h5s + 8 * L_);   // KS_PAD u16

    const int tid = threadIdx.x;
    for (int idx = tid; idx < L_ * L_; idx += 256) {
        int o = idx / L_, d = idx - o * L_;
        sW3[o * 69 + d] = W3[idx];
        sW4[o * 69 + d] = W4[idx];
        sW5[o * 69 + d] = W5[idx];
    }
    for (int idx = tid; idx < L_; idx += 256) {
        sb3[idx] = b3[idx]; sb4[idx] = b4[idx]; sb5[idx] = b5[idx];
    }
    for (int idx = tid; idx < KS_PAD; idx += 256)
        prS[idx] = gpairs[idx];
    __syncthreads();

    const int lane = tid & 31, w = tid >> 5;
    const int row = blockIdx.x * 8 + w;
    const float* murow  = mu + (size_t)row * L_;
    const float* lvrow  = logvar + (size_t)row * L_;
    const float* epsrow = eps + (size_t)row * L_;
    float* zw  = zs + w * L_;
    float* h3w = h3s + w * L_;
    float* h4w = h4s + w * L_;
    float* h5w = h5s + w * L_;

    float yp = 0.f;
    for (int o = lane; o < L_; o += 32) {
        float m_ = murow[o];
        zw[o] = m_ + epsrow[o] * expf(0.5f * lvrow[o]);
        yp += m_ * fcy_w[o];
    }
#pragma unroll
    for (int off = 16; off; off >>= 1) yp += __shfl_xor_sync(0xffffffffu, yp, off);
    if (lane == 0) y[row] = yp + fcy_b[0];
    __syncwarp();

    for (int o = lane; o < L_; o += 32) {
        float sacc = sb3[o];
        const float* wr = sW3 + o * 69;
#pragma unroll 4
        for (int d = 0; d < L_; d++) sacc += zw[d] * wr[d];
        h3w[o] = sacc;                  // branch 0: NO sigmoid
    }
    __syncwarp();
    for (int o = lane; o < L_; o += 32) {
        float sacc = sb4[o];
        const float* wr = sW4 + o * 69;
#pragma unroll 4
        for (int d = 0; d < L_; d++) sacc += h3w[d] * wr[d];
        h4w[o] = 1.0f / (1.0f + expf(-sacc));
    }
    __syncwarp();
    for (int o = lane; o < L_; o += 32) {
        float sacc = sb5[o];
        const float* wr = sW5 + o * 69;
#pragma unroll 4
        for (int d = 0; d < L_; d++) sacc += h4w[d] * wr[d];
        h5w[o] = sacc;
    }
    __syncwarp();

    // write a16r row: pair products, vectorized u32 (2 halves per store)
    __half* dst = a16r + (size_t)row * KS_PAD;
    for (int p2 = lane; p2 < KS_PAD / 2; p2 += 32) {
        int p = p2 * 2;
        uint16_t pr0 = prS[p], pr1 = prS[p + 1];
        float f0 = h5w[pr0 >> 8] * h5w[pr0 & 255];
        float f1 = h5w[pr1 >> 8] * h5w[pr1 & 255];
        *reinterpret_cast<uint32_t*>(dst + p) = pack_h2(f0, f1);
    }
}

// ============================ launch ============================
extern "C" void kernel_launch(void* const* d_in, const int* in_sizes, int n_in,
                              void* d_out, int out_size)
{
    const float* x      = (const float*)d_in[0];
    const float* eps    = (const float*)d_in[1];
    const float* fc11_w = (const float*)d_in[2];
    const float* fc11_b = (const float*)d_in[3];
    const float* fc12_w = (const float*)d_in[4];
    const float* fc12_b = (const float*)d_in[5];
    const float* fc21_w = (const float*)d_in[6];
    const float* fc21_b = (const float*)d_in[7];
    const float* fc22_w = (const float*)d_in[8];
    const float* fc22_b = (const float*)d_in[9];
    const float* W3     = (const float*)d_in[10];
    const float* b3     = (const float*)d_in[11];
    const float* W4     = (const float*)d_in[12];
    const float* b4     = (const float*)d_in[13];
    const float* W5     = (const float*)d_in[14];
    const float* b5     = (const float*)d_in[15];
    const float* fc6_w  = (const float*)d_in[16];
    const float* fc6_b  = (const float*)d_in[17];
    const float* fcy_w  = (const float*)d_in[18];
    const float* fcy_b  = (const float*)d_in[19];

    float* out   = (float*)d_out;
    float* recon = out;
    float* mu    = out + (size_t)B_ * D_;
    float* lv    = mu + (size_t)B_ * L_;
    float* y     = lv + (size_t)B_ * L_;

    __half*   x16;  cudaGetSymbolAddress((void**)&x16, g_x16);
    __half*   h16;  cudaGetSymbolAddress((void**)&h16, g_h16);
    __half*   w1h;  cudaGetSymbolAddress((void**)&w1h, g_w1h);
    __half*   w2h;  cudaGetSymbolAddress((void**)&w2h, g_w2h);
    __half*   w6s;  cudaGetSymbolAddress((void**)&w6s, g_w6s);
    __half*   a16r; cudaGetSymbolAddress((void**)&a16r, g_a16r);
    uint16_t* prs;  cudaGetSymbolAddress((void**)&prs, g_pairs);
    float*    b1;   cudaGetSymbolAddress((void**)&b1,  g_b1);

    // fused pre-pass (1 launch) + pair table + symmetric weight fold
    prep_all<<<1024, 256>>>((const float4*)x,
                            (const float4*)fc11_w, (const float4*)fc12_w,
                            (const float4*)fc21_w, (const float4*)fc22_w,
                            (const float4*)fc11_b, (const float4*)fc12_b,
                            (uint2*)x16, (uint2*)w1h, (uint2*)w2h, (float4*)b1);
    build_pairs<<<(KS_PAD + 255) / 256, 256>>>(prs);
    build_w6s<<<D_, 256>>>(fc6_w, prs, w6s);

    const size_t smemBig  = (size_t)3 * (ASTG_B + BSTG_B);                      // 165888
    const size_t smemHead = (size_t)6 * STAGE_BYTES;                            // 61440
    const size_t smemMid  = (size_t)(3 * L_ * 69 + 3 * L_ + 4 * 8 * L_) * 4
                          + KS_PAD * 2;

    cudaFuncSetAttribute(gemm_big<0>,    cudaFuncAttributeMaxDynamicSharedMemorySize, (int)smemBig);
    cudaFuncSetAttribute(gemm_big<1>,    cudaFuncAttributeMaxDynamicSharedMemorySize, (int)smemBig);
    cudaFuncSetAttribute(gemm_head,      cudaFuncAttributeMaxDynamicSharedMemorySize, (int)smemHead);
    cudaFuncSetAttribute(mid_a16r_kernel,cudaFuncAttributeMaxDynamicSharedMemorySize, (int)smemMid);

    // 1) h16 = fp16(relu(x @ [fc11|fc12]^T + b))   [4096 x 2048]
    gemm_big<0><<<dim3(2 * E_ / BN2, B_ / BM), THREADS2, smemBig>>>(
        x16, D_, w1h, b1, h16, 2 * E_, 2 * E_, D_, 2 * E_);

    // 2) mu / logvar heads  [4096 x 68], z-batched
    gemm_head<<<dim3(1, B_ / BM, 2), THREADS, smemHead>>>(
        h16, w2h, fc21_b, fc22_b, mu, B_ * L_);

    // 3) reparam + y + decoder branch 0 + recon-A materialization (fused)
    mid_a16r_kernel<<<B_ / 8, 256, smemMid>>>(
        mu, lv, eps, W3, b3, W4, b4, W5, b5, fcy_w, fcy_b, prs, a16r, y);

    // 4) recon = sigmoid(a16r @ w6s^T + b)  [4096 x 4624], K=2368
    gemm_big<1><<<dim3((D_ + BN2 - 1) / BN2, B_ / BM), THREADS2, smemBig>>>(
        a16r, KS_PAD, w6s, fc6_b, recon, D_, D_, KS_PAD, D_);
}